// round 16
// baseline (speedup 1.0000x reference)
#include <cuda_runtime.h>
#include <cuda_fp16.h>
#include <cstdint>
#include <math.h>

#define D_MODEL 1024
#define T_SEQ   2048
#define B_BATCH 4

// Scratch (allocation-free rule: __device__ globals)
__device__ __half g_xh[(size_t)B_BATCH * T_SEQ * D_MODEL];        // 16 MB
__device__ __half g_wqkvh[(size_t)D_MODEL * 3 * D_MODEL];         // 6 MB
__device__ __half g_wprojh[(size_t)D_MODEL * D_MODEL];            // 2 MB
__device__ __half g_qkv[(size_t)B_BATCH * T_SEQ * 3 * D_MODEL];   // 48 MB
__device__ float  g_scores[(size_t)B_BATCH * T_SEQ * T_SEQ];      // 64 MB
__device__ __half g_p[(size_t)B_BATCH * T_SEQ * T_SEQ];           // 32 MB
__device__ __half g_att[(size_t)B_BATCH * T_SEQ * D_MODEL];       // 16 MB

__device__ __forceinline__ uint32_t smem_u32(const void* p) {
    uint32_t a;
    asm("{ .reg .u64 t; cvta.to.shared.u64 t, %1; cvt.u32.u64 %0, t; }"
        : "=r"(a) : "l"(p));
    return a;
}

__device__ __forceinline__ uint32_t pack2(float x, float y) {
    __half2 h = __floats2half2_rn(x, y);
    return *(uint32_t*)&h;
}

__device__ __forceinline__ void mma16(float* acc, const uint32_t* a, const uint32_t* b) {
    asm volatile(
        "mma.sync.aligned.m16n8k16.row.col.f32.f16.f16.f32 "
        "{%0,%1,%2,%3}, {%4,%5,%6,%7}, {%8,%9}, {%0,%1,%2,%3};"
        : "+f"(acc[0]), "+f"(acc[1]), "+f"(acc[2]), "+f"(acc[3])
        : "r"(a[0]), "r"(a[1]), "r"(a[2]), "r"(a[3]), "r"(b[0]), "r"(b[1]));
}

__device__ __forceinline__ void ldsm4(uint32_t* r, uint32_t a) {
    asm volatile("ldmatrix.sync.aligned.m8n8.x4.shared.b16 {%0,%1,%2,%3}, [%4];"
        : "=r"(r[0]), "=r"(r[1]), "=r"(r[2]), "=r"(r[3]) : "r"(a));
}
__device__ __forceinline__ void ldsm4t(uint32_t* r, uint32_t a) {
    asm volatile("ldmatrix.sync.aligned.m8n8.x4.trans.shared.b16 {%0,%1,%2,%3}, [%4];"
        : "=r"(r[0]), "=r"(r[1]), "=r"(r[2]), "=r"(r[3]) : "r"(a));
}

__device__ __forceinline__ void cpa16(uint32_t dst, const __half* src) {
    asm volatile("cp.async.cg.shared.global [%0], [%1], 16;"
        :: "r"(dst), "l"(__cvta_generic_to_global(src)));
}
#define CP_COMMIT() asm volatile("cp.async.commit_group;" ::: "memory")
#define CP_WAIT(n)  asm volatile("cp.async.wait_group %0;" :: "n"(n) : "memory")

// ---------------------------------------------------------------------------
// fp16 GEMM, fp32 accumulate: C = scale*(A @ op(B)) (+bias).
// A: [M,K] fp16 row-major.
// BTRANS=1: B is [K,N] -> smem [k][n] stride 264, ldmatrix.trans
// BTRANS=0: B is [N,K] -> smem [n][k] stride 40, ldmatrix (same as A)
// SKIPUP:  cull blocks col0 > row0.  KCAUSAL: K ends at row0+128.
// REVY:    reverse blockIdx.y so heavy (large-row0) tiles launch first.
// 128x256 tile, BK=32, 4-stage cp.async, 512 thr (16 warps 2Mx8N,
// warp tile 64x32). FROZEN R8 pipeline shape; prefetch AFTER the MMA block
// (cp.async shares the LSU with ldmatrix — issuing first starves fragments).
// B-fragments loaded before A-fragments (first MMA gated by last-issued load).
// ---------------------------------------------------------------------------
template<typename TC, int BTRANS, bool SKIPUP, bool KCAUSAL, bool BIAS, bool REVY>
__global__ __launch_bounds__(512) void mm_h(
    const __half* __restrict__ A, const __half* __restrict__ B,
    TC* __restrict__ C, const float* __restrict__ bias,
    int K, int lda, int ldb, int ldc,
    long bA, long bB, long bC, float scale)
{
    constexpr int BM = 128, BN = 256, BK = 32, S = 4;
    constexpr int AST = 40, BSTT = 264, BSTN = 40;     // smem strides (halves)
    constexpr int ABYTES = 128 * AST * 2;              // 10240
    constexpr int BBYTES = BTRANS ? 32 * BSTT * 2 : 256 * BSTN * 2;
    constexpr int STG = ABYTES + BBYTES;               // bytes per stage
    extern __shared__ char dsm[];

    const int by = REVY ? (gridDim.y - 1 - blockIdx.y) : blockIdx.y;
    const int row0 = by * BM, col0 = blockIdx.x * BN;
    if (SKIPUP && col0 > row0) return;

    A += (long)blockIdx.z * bA + (long)row0 * lda;
    B += (long)blockIdx.z * bB + (BTRANS ? (long)col0 : (long)col0 * ldb);
    C += (long)blockIdx.z * bC + (long)row0 * ldc + col0;

    const int tid = threadIdx.x, wid = tid >> 5, lane = tid & 31;
    const int g = lane >> 2, t = lane & 3;
    const int grp = lane >> 3, li = lane & 7;
    const int mbase = (wid >> 3) * 64;      // 2 M-warps
    const int nbase = (wid & 7) * 32;       // 8 N-warps

    int Kend = K;
    if (KCAUSAL) { int ke = row0 + BM; Kend = ke < K ? ke : K; }
    const int NC = Kend / BK;

    const uint32_t smb = smem_u32(dsm);

    // cp.async per-thread coords (512 threads)
    const int amRow = tid >> 2, ak4 = tid & 3;          // A: 512 x 16B, 1/thread
    const __half* aSrc = A + (long)amRow * lda + ak4 * 8;
    const uint32_t aDst = smb + (amRow * AST + ak4 * 8) * 2;

    const __half* bSrc;
    uint32_t bDst, bItD;
    long bItS, bCst;
    if (BTRANS) {
        const int bk = tid >> 5, bn8 = tid & 31;        // 32 k-rows x 32 chunks
        bSrc = B + (long)bk * ldb + bn8 * 8;
        bDst = smb + ABYTES + (bk * BSTT + bn8 * 8) * 2;
        bItS = (long)16 * ldb;  bItD = 16 * BSTT * 2;
        bCst = (long)32 * ldb;
    } else {
        const int bn = tid >> 2, bk4 = tid & 3;         // 256 n-rows x 4 chunks
        bSrc = B + (long)bn * ldb + bk4 * 8;
        bDst = smb + ABYTES + (bn * BSTN + bk4 * 8) * 2;
        bItS = (long)128 * ldb; bItD = 128 * BSTN * 2;
        bCst = 32;
    }

    auto issue = [&](int c) {
        const uint32_t bo = (c & (S - 1)) * STG;
        cpa16(aDst + bo, aSrc + (long)c * 32);
        const __half* bs = bSrc + (long)c * bCst;
        cpa16(bDst + bo, bs);
        cpa16(bDst + bo + bItD, bs + bItS);
    };

    #pragma unroll
    for (int s = 0; s < S - 1; s++) {
        if (s < NC) issue(s);
        CP_COMMIT();
    }

    // fragment base addresses
    const int aR0 = mbase + (grp & 1) * 8 + li;
    const uint32_t aFrag = smb + (aR0 * AST + (grp >> 1) * 8) * 2;
    uint32_t bFrag;
    if (BTRANS) {
        const int kR0 = (grp & 1) * 8 + li;
        bFrag = smb + ABYTES + (kR0 * BSTT + nbase + (grp >> 1) * 8) * 2;
    } else {
        const int nR0 = nbase + (grp >> 1) * 8 + li;
        bFrag = smb + ABYTES + (nR0 * BSTN + (grp & 1) * 8) * 2;
    }

    float acc[4][4][4];
    #pragma unroll
    for (int i = 0; i < 4; i++)
        #pragma unroll
        for (int j = 0; j < 4; j++)
            #pragma unroll
            for (int q = 0; q < 4; q++) acc[i][j][q] = 0.f;

    for (int c = 0; c < NC; c++) {
        CP_WAIT(S - 2);
        __syncthreads();
        const uint32_t bo = (c & (S - 1)) * STG;
        #pragma unroll
        for (int ks = 0; ks < 2; ks++) {
            uint32_t a[4][4], bb[2][4];
            // B first: first MMA is gated by the last-issued fragment load
            #pragma unroll
            for (int np = 0; np < 2; np++) {
                if (BTRANS) ldsm4t(bb[np], bFrag + bo + ks * (16 * BSTT * 2) + np * 32);
                else        ldsm4 (bb[np], bFrag + bo + np * (16 * BSTN * 2) + ks * 32);
            }
            #pragma unroll
            for (int mt = 0; mt < 4; mt++)
                ldsm4(a[mt], aFrag + bo + mt * (16 * AST * 2) + ks * 32);
            #pragma unroll
            for (int mt = 0; mt < 4; mt++)
                #pragma unroll
                for (int nt = 0; nt < 4; nt++)
                    mma16(acc[mt][nt], a[mt], &bb[nt >> 1][(nt & 1) * 2]);
        }
        // prefetch AFTER the MMA block: ldmatrix ops have drained from the LSU
        const int nx = c + S - 1;
        if (nx < NC) issue(nx);
        CP_COMMIT();
    }

    // epilogue
    #pragma unroll
    for (int mt = 0; mt < 4; mt++) {
        const int r0 = mbase + mt * 16 + g;
        #pragma unroll
        for (int nt = 0; nt < 4; nt++) {
            const int cc = nbase + nt * 8 + 2 * t;
            float bx = 0.f, byv = 0.f;
            if (BIAS) { bx = bias[col0 + cc]; byv = bias[col0 + cc + 1]; }
            float v00 = acc[mt][nt][0] * scale + bx;
            float v01 = acc[mt][nt][1] * scale + byv;
            float v10 = acc[mt][nt][2] * scale + bx;
            float v11 = acc[mt][nt][3] * scale + byv;
            if constexpr (sizeof(TC) == 2) {
                *(__half2*)((__half*)C + (long)r0 * ldc + cc) = __floats2half2_rn(v00, v01);
                *(__half2*)((__half*)C + (long)(r0 + 8) * ldc + cc) = __floats2half2_rn(v10, v11);
            } else {
                *(float2*)((float*)C + (long)r0 * ldc + cc) = make_float2(v00, v01);
                *(float2*)((float*)C + (long)(r0 + 8) * ldc + cc) = make_float2(v10, v11);
            }
        }
    }
}

// smem sizes per variant (host mirror of STG)
#define SMEM_BT (4 * (10240 + 32 * 264 * 2))    // BTRANS=1: 108544
#define SMEM_BN (4 * (10240 + 256 * 40 * 2))    // BTRANS=0: 122880

// ---------------------------------------------------------------------------
// Causal softmax, vectorized: each thread owns 8 contiguous elements
// (2x float4 load, 1x uint4 = 4x half2 store). fp32 scores -> fp16 P.
// Writes only up to the 128-aligned block end (all P@V reads). Unwritten
// score regions are 0.0 (zero-init globals), masked to -inf before max.
// ---------------------------------------------------------------------------
__global__ __launch_bounds__(256) void softmax_causal_k(
    const float* __restrict__ scores, __half* __restrict__ P)
{
    const int tq = blockIdx.x, b = blockIdx.y;
    const float* row = scores + ((size_t)b * T_SEQ + tq) * T_SEQ;
    __half* prow = P + ((size_t)b * T_SEQ + tq) * T_SEQ;
    const int n = tq + 1;
    const int nw = ((tq >> 7) + 1) << 7;
    const int tid = threadIdx.x, wid = tid >> 5, lane = tid & 31;
    const int i0 = tid * 8;

    __shared__ float red[8];

    float4 v0 = *(const float4*)(row + i0);
    float4 v1 = *(const float4*)(row + i0 + 4);
    float e[8] = {v0.x, v0.y, v0.z, v0.w, v1.x, v1.y, v1.z, v1.w};

    float m = -INFINITY;
    #pragma unroll
    for (int j = 0; j < 8; j++) {
        if (i0 + j >= n) e[j] = -INFINITY;
        m = fmaxf(m, e[j]);
    }
    #pragma unroll
    for (int o = 16; o; o >>= 1) m = fmaxf(m, __shfl_xor_sync(~0u, m, o));
    if (lane == 0) red[wid] = m;
    __syncthreads();
    m = red[0];
    #pragma unroll
    for (int w = 1; w < 8; w++) m = fmaxf(m, red[w]);

    float s = 0.f;
    #pragma unroll
    for (int j = 0; j < 8; j++) { e[j] = __expf(e[j] - m); s += e[j]; }
    #pragma unroll
    for (int o = 16; o; o >>= 1) s += __shfl_xor_sync(~0u, s, o);
    __syncthreads();
    if (lane == 0) red[wid] = s;
    __syncthreads();
    s = 0.f;
    #pragma unroll
    for (int w = 0; w < 8; w++) s += red[w];
    const float inv = 1.f / s;

    if (i0 < nw) {
        uint4 o;
        o.x = pack2(e[0] * inv, e[1] * inv);
        o.y = pack2(e[2] * inv, e[3] * inv);
        o.z = pack2(e[4] * inv, e[5] * inv);
        o.w = pack2(e[6] * inv, e[7] * inv);
        *(uint4*)(prow + i0) = o;
    }
}

// fused fp32 -> fp16 bulk convert for x, w_qkv, w_proj in one launch.
// blocks [0,4096): x, [4096,5632): w_qkv, [5632,6144): w_proj
__global__ __launch_bounds__(256) void cvt_all_k(
    const float* __restrict__ x, __half* __restrict__ xh,
    const float* __restrict__ wq, __half* __restrict__ wqh,
    const float* __restrict__ wp, __half* __restrict__ wph)
{
    const float* in;
    __half* out;
    size_t base;
    const int bx = blockIdx.x;
    if (bx < 4096)      { in = x;  out = xh;  base = (size_t)bx * 2048; }
    else if (bx < 5632) { in = wq; out = wqh; base = (size_t)(bx - 4096) * 2048; }
    else                { in = wp; out = wph; base = (size_t)(bx - 5632) * 2048; }
    const size_t i = base + (size_t)threadIdx.x * 8;
    float4 v0 = *(const float4*)(in + i);
    float4 v1 = *(const float4*)(in + i + 4);
    uint4 o;
    o.x = pack2(v0.x, v0.y); o.y = pack2(v0.z, v0.w);
    o.z = pack2(v1.x, v1.y); o.w = pack2(v1.z, v1.w);
    *(uint4*)(out + i) = o;
}

extern "C" void kernel_launch(void* const* d_in, const int* in_sizes, int n_in,
                              void* d_out, int out_size)
{
    (void)in_sizes; (void)n_in; (void)out_size;
    const float* x      = (const float*)d_in[0];  // [4,2048,1024]
    const float* w_qkv  = (const float*)d_in[1];  // [1024,3072]
    const float* w_proj = (const float*)d_in[2];  // [1024,1024]
    const float* b_proj = (const float*)d_in[3];  // [1024]
    float* out          = (float*)d_out;          // [4,2048,1024]

    __half *xh, *wqkvh, *wprojh, *qkv, *p, *att;
    float *scores;
    cudaGetSymbolAddress((void**)&xh,     g_xh);
    cudaGetSymbolAddress((void**)&wqkvh,  g_wqkvh);
    cudaGetSymbolAddress((void**)&wprojh, g_wprojh);
    cudaGetSymbolAddress((void**)&qkv,    g_qkv);
    cudaGetSymbolAddress((void**)&scores, g_scores);
    cudaGetSymbolAddress((void**)&p,      g_p);
    cudaGetSymbolAddress((void**)&att,    g_att);

    const int D = D_MODEL, T = T_SEQ;
    const dim3 blk(512);

    cudaFuncSetAttribute((const void*)mm_h<__half, 1, false, false, false, false>,
                         cudaFuncAttributeMaxDynamicSharedMemorySize, SMEM_BT);
    cudaFuncSetAttribute((const void*)mm_h<float, 0, true, false, false, true>,
                         cudaFuncAttributeMaxDynamicSharedMemorySize, SMEM_BN);
    cudaFuncSetAttribute((const void*)mm_h<__half, 1, false, true, false, true>,
                         cudaFuncAttributeMaxDynamicSharedMemorySize, SMEM_BT);
    cudaFuncSetAttribute((const void*)mm_h<float, 1, false, false, true, false>,
                         cudaFuncAttributeMaxDynamicSharedMemorySize, SMEM_BT);

    // 0) fused fp32 -> fp16 conversions (one launch)
    cvt_all_k<<<6144, 256>>>(x, xh, w_qkv, wqkvh, w_proj, wprojh);

    // 1) QKV = Xh @ Wqkv -> fp16 : [8192,3072], K=1024, B [K,N]
    mm_h<__half, 1, false, false, false, false>
        <<<dim3(3 * D / 256, B_BATCH * T / 128, 1), blk, SMEM_BT>>>(
        xh, wqkvh, qkv, nullptr, D, D, 3 * D, 3 * D, 0, 0, 0, 1.f);

    // 2) scores = Q @ K^T / 32 (fp32), causal cull, heavy-first; K-matrix [N,K]
    mm_h<float, 0, true, false, false, true>
        <<<dim3(T / 256, T / 128, B_BATCH), blk, SMEM_BN>>>(
        qkv, qkv + D, scores, nullptr, D, 3 * D, 3 * D, T,
        (long)T * 3 * D, (long)T * 3 * D, (long)T * T, 1.f / 32.f);

    // 3) causal softmax -> fp16 P (tail zero up to 128-block end)
    softmax_causal_k<<<dim3(T, B_BATCH), 256>>>(scores, p);

    // 4) att = P @ V -> fp16 : causal K-end, heavy-first; V [K,N]
    mm_h<__half, 1, false, true, false, true>
        <<<dim3(D / 256, T / 128, B_BATCH), blk, SMEM_BT>>>(
        p, qkv + 2 * D, att, nullptr, T, T, 3 * D, D,
        (long)T * T, (long)T * 3 * D, (long)T * D, 1.f);

    // 5) out = att @ Wproj + b : [8192,1024], K=1024, B [K,N]
    mm_h<float, 1, false, false, true, false>
        <<<dim3(D / 256, B_BATCH * T / 128, 1), blk, SMEM_BT>>>(
        att, wprojh, out, b_proj, D, D, D, D, 0, 0, 0, 1.f);
}

// round 17
// speedup vs baseline: 1.0108x; 1.0108x over previous
#include <cuda_runtime.h>
#include <cuda_fp16.h>
#include <cstdint>
#include <math.h>

#define D_MODEL 1024
#define T_SEQ   2048
#define B_BATCH 4

// Scratch (allocation-free rule: __device__ globals)
__device__ __half g_xh[(size_t)B_BATCH * T_SEQ * D_MODEL];        // 16 MB
__device__ __half g_wqkvh[(size_t)D_MODEL * 3 * D_MODEL];         // 6 MB
__device__ __half g_wprojh[(size_t)D_MODEL * D_MODEL];            // 2 MB
__device__ __half g_qkv[(size_t)B_BATCH * T_SEQ * 3 * D_MODEL];   // 48 MB
__device__ float  g_scores[(size_t)B_BATCH * T_SEQ * T_SEQ];      // 64 MB
__device__ __half g_p[(size_t)B_BATCH * T_SEQ * T_SEQ];           // 32 MB
__device__ __half g_att[(size_t)B_BATCH * T_SEQ * D_MODEL];       // 16 MB

__device__ __forceinline__ uint32_t smem_u32(const void* p) {
    uint32_t a;
    asm("{ .reg .u64 t; cvta.to.shared.u64 t, %1; cvt.u32.u64 %0, t; }"
        : "=r"(a) : "l"(p));
    return a;
}

__device__ __forceinline__ uint32_t pack2(float x, float y) {
    __half2 h = __floats2half2_rn(x, y);
    return *(uint32_t*)&h;
}

__device__ __forceinline__ void mma16(float* acc, const uint32_t* a, const uint32_t* b) {
    asm volatile(
        "mma.sync.aligned.m16n8k16.row.col.f32.f16.f16.f32 "
        "{%0,%1,%2,%3}, {%4,%5,%6,%7}, {%8,%9}, {%0,%1,%2,%3};"
        : "+f"(acc[0]), "+f"(acc[1]), "+f"(acc[2]), "+f"(acc[3])
        : "r"(a[0]), "r"(a[1]), "r"(a[2]), "r"(a[3]), "r"(b[0]), "r"(b[1]));
}

__device__ __forceinline__ void ldsm4(uint32_t* r, uint32_t a) {
    asm volatile("ldmatrix.sync.aligned.m8n8.x4.shared.b16 {%0,%1,%2,%3}, [%4];"
        : "=r"(r[0]), "=r"(r[1]), "=r"(r[2]), "=r"(r[3]) : "r"(a));
}
__device__ __forceinline__ void ldsm4t(uint32_t* r, uint32_t a) {
    asm volatile("ldmatrix.sync.aligned.m8n8.x4.trans.shared.b16 {%0,%1,%2,%3}, [%4];"
        : "=r"(r[0]), "=r"(r[1]), "=r"(r[2]), "=r"(r[3]) : "r"(a));
}

__device__ __forceinline__ void cpa16(uint32_t dst, const __half* src) {
    asm volatile("cp.async.cg.shared.global [%0], [%1], 16;"
        :: "r"(dst), "l"(__cvta_generic_to_global(src)));
}
#define CP_COMMIT() asm volatile("cp.async.commit_group;" ::: "memory")
#define CP_WAIT(n)  asm volatile("cp.async.wait_group %0;" :: "n"(n) : "memory")

// ---------------------------------------------------------------------------
// fp16 GEMM, fp32 accumulate: C = scale*(A @ op(B)) (+bias).
// A: [M,K] fp16 row-major.
// BTRANS=1: B is [K,N] -> smem [k][n] stride 264, ldmatrix.trans
// BTRANS=0: B is [N,K] -> smem [n][k] stride 40, ldmatrix (same as A)
// SKIPUP:  cull blocks col0 > row0.  KCAUSAL: K ends at row0+128.
// REVY:    reverse blockIdx.y so heavy (large-row0) tiles launch first.
// 128x256 tile, BK=32, 4-stage cp.async, 512 thr (16 warps 2Mx8N,
// warp tile 64x32). FROZEN R14 configuration: prefetch AFTER the MMA block
// (cp.async shares the LSU with ldmatrix), A-fragments then B-fragments.
// ---------------------------------------------------------------------------
template<typename TC, int BTRANS, bool SKIPUP, bool KCAUSAL, bool BIAS, bool REVY>
__global__ __launch_bounds__(512) void mm_h(
    const __half* __restrict__ A, const __half* __restrict__ B,
    TC* __restrict__ C, const float* __restrict__ bias,
    int K, int lda, int ldb, int ldc,
    long bA, long bB, long bC, float scale)
{
    constexpr int BM = 128, BN = 256, BK = 32, S = 4;
    constexpr int AST = 40, BSTT = 264, BSTN = 40;     // smem strides (halves)
    constexpr int ABYTES = 128 * AST * 2;              // 10240
    constexpr int BBYTES = BTRANS ? 32 * BSTT * 2 : 256 * BSTN * 2;
    constexpr int STG = ABYTES + BBYTES;               // bytes per stage
    extern __shared__ char dsm[];

    const int by = REVY ? (gridDim.y - 1 - blockIdx.y) : blockIdx.y;
    const int row0 = by * BM, col0 = blockIdx.x * BN;
    if (SKIPUP && col0 > row0) return;

    A += (long)blockIdx.z * bA + (long)row0 * lda;
    B += (long)blockIdx.z * bB + (BTRANS ? (long)col0 : (long)col0 * ldb);
    C += (long)blockIdx.z * bC + (long)row0 * ldc + col0;

    const int tid = threadIdx.x, wid = tid >> 5, lane = tid & 31;
    const int g = lane >> 2, t = lane & 3;
    const int grp = lane >> 3, li = lane & 7;
    const int mbase = (wid >> 3) * 64;      // 2 M-warps
    const int nbase = (wid & 7) * 32;       // 8 N-warps

    int Kend = K;
    if (KCAUSAL) { int ke = row0 + BM; Kend = ke < K ? ke : K; }
    const int NC = Kend / BK;

    const uint32_t smb = smem_u32(dsm);

    // cp.async per-thread coords (512 threads)
    const int amRow = tid >> 2, ak4 = tid & 3;          // A: 512 x 16B, 1/thread
    const __half* aSrc = A + (long)amRow * lda + ak4 * 8;
    const uint32_t aDst = smb + (amRow * AST + ak4 * 8) * 2;

    const __half* bSrc;
    uint32_t bDst, bItD;
    long bItS, bCst;
    if (BTRANS) {
        const int bk = tid >> 5, bn8 = tid & 31;        // 32 k-rows x 32 chunks
        bSrc = B + (long)bk * ldb + bn8 * 8;
        bDst = smb + ABYTES + (bk * BSTT + bn8 * 8) * 2;
        bItS = (long)16 * ldb;  bItD = 16 * BSTT * 2;
        bCst = (long)32 * ldb;
    } else {
        const int bn = tid >> 2, bk4 = tid & 3;         // 256 n-rows x 4 chunks
        bSrc = B + (long)bn * ldb + bk4 * 8;
        bDst = smb + ABYTES + (bn * BSTN + bk4 * 8) * 2;
        bItS = (long)128 * ldb; bItD = 128 * BSTN * 2;
        bCst = 32;
    }

    auto issue = [&](int c) {
        const uint32_t bo = (c & (S - 1)) * STG;
        cpa16(aDst + bo, aSrc + (long)c * 32);
        const __half* bs = bSrc + (long)c * bCst;
        cpa16(bDst + bo, bs);
        cpa16(bDst + bo + bItD, bs + bItS);
    };

    #pragma unroll
    for (int s = 0; s < S - 1; s++) {
        if (s < NC) issue(s);
        CP_COMMIT();
    }

    // fragment base addresses
    const int aR0 = mbase + (grp & 1) * 8 + li;
    const uint32_t aFrag = smb + (aR0 * AST + (grp >> 1) * 8) * 2;
    uint32_t bFrag;
    if (BTRANS) {
        const int kR0 = (grp & 1) * 8 + li;
        bFrag = smb + ABYTES + (kR0 * BSTT + nbase + (grp >> 1) * 8) * 2;
    } else {
        const int nR0 = nbase + (grp >> 1) * 8 + li;
        bFrag = smb + ABYTES + (nR0 * BSTN + (grp & 1) * 8) * 2;
    }

    float acc[4][4][4];
    #pragma unroll
    for (int i = 0; i < 4; i++)
        #pragma unroll
        for (int j = 0; j < 4; j++)
            #pragma unroll
            for (int q = 0; q < 4; q++) acc[i][j][q] = 0.f;

    for (int c = 0; c < NC; c++) {
        CP_WAIT(S - 2);
        __syncthreads();
        const uint32_t bo = (c & (S - 1)) * STG;
        #pragma unroll
        for (int ks = 0; ks < 2; ks++) {
            uint32_t a[4][4], bb[2][4];
            #pragma unroll
            for (int mt = 0; mt < 4; mt++)
                ldsm4(a[mt], aFrag + bo + mt * (16 * AST * 2) + ks * 32);
            #pragma unroll
            for (int np = 0; np < 2; np++) {
                if (BTRANS) ldsm4t(bb[np], bFrag + bo + ks * (16 * BSTT * 2) + np * 32);
                else        ldsm4 (bb[np], bFrag + bo + np * (16 * BSTN * 2) + ks * 32);
            }
            #pragma unroll
            for (int mt = 0; mt < 4; mt++)
                #pragma unroll
                for (int nt = 0; nt < 4; nt++)
                    mma16(acc[mt][nt], a[mt], &bb[nt >> 1][(nt & 1) * 2]);
        }
        // prefetch AFTER the MMA block: ldmatrix ops have drained from the LSU
        const int nx = c + S - 1;
        if (nx < NC) issue(nx);
        CP_COMMIT();
    }

    // epilogue
    #pragma unroll
    for (int mt = 0; mt < 4; mt++) {
        const int r0 = mbase + mt * 16 + g;
        #pragma unroll
        for (int nt = 0; nt < 4; nt++) {
            const int cc = nbase + nt * 8 + 2 * t;
            float bx = 0.f, byv = 0.f;
            if (BIAS) { bx = bias[col0 + cc]; byv = bias[col0 + cc + 1]; }
            float v00 = acc[mt][nt][0] * scale + bx;
            float v01 = acc[mt][nt][1] * scale + byv;
            float v10 = acc[mt][nt][2] * scale + bx;
            float v11 = acc[mt][nt][3] * scale + byv;
            if constexpr (sizeof(TC) == 2) {
                *(__half2*)((__half*)C + (long)r0 * ldc + cc) = __floats2half2_rn(v00, v01);
                *(__half2*)((__half*)C + (long)(r0 + 8) * ldc + cc) = __floats2half2_rn(v10, v11);
            } else {
                *(float2*)((float*)C + (long)r0 * ldc + cc) = make_float2(v00, v01);
                *(float2*)((float*)C + (long)(r0 + 8) * ldc + cc) = make_float2(v10, v11);
            }
        }
    }
}

// smem sizes per variant (host mirror of STG)
#define SMEM_BT (4 * (10240 + 32 * 264 * 2))    // BTRANS=1: 108544
#define SMEM_BN (4 * (10240 + 256 * 40 * 2))    // BTRANS=0: 122880

// ---------------------------------------------------------------------------
// Causal softmax, vectorized + causally-bounded loads: each thread owns 8
// contiguous elements; threads beyond the 128-aligned causal end skip their
// gmem loads entirely (those regions contribute -inf/0 exactly as before).
// fp32 scores -> normalized fp16 P, written only up to the block end.
// ---------------------------------------------------------------------------
__global__ __launch_bounds__(256) void softmax_causal_k(
    const float* __restrict__ scores, __half* __restrict__ P)
{
    const int tq = blockIdx.x, b = blockIdx.y;
    const float* row = scores + ((size_t)b * T_SEQ + tq) * T_SEQ;
    __half* prow = P + ((size_t)b * T_SEQ + tq) * T_SEQ;
    const int n = tq + 1;
    const int nw = ((tq >> 7) + 1) << 7;     // 128-aligned causal end
    const int tid = threadIdx.x, wid = tid >> 5, lane = tid & 31;
    const int i0 = tid * 8;
    const bool live = (i0 < nw);

    __shared__ float red[8];

    float e[8];
    if (live) {
        float4 v0 = *(const float4*)(row + i0);
        float4 v1 = *(const float4*)(row + i0 + 4);
        e[0] = v0.x; e[1] = v0.y; e[2] = v0.z; e[3] = v0.w;
        e[4] = v1.x; e[5] = v1.y; e[6] = v1.z; e[7] = v1.w;
    } else {
        #pragma unroll
        for (int j = 0; j < 8; j++) e[j] = -INFINITY;
    }

    float m = -INFINITY;
    #pragma unroll
    for (int j = 0; j < 8; j++) {
        if (i0 + j >= n) e[j] = -INFINITY;
        m = fmaxf(m, e[j]);
    }
    #pragma unroll
    for (int o = 16; o; o >>= 1) m = fmaxf(m, __shfl_xor_sync(~0u, m, o));
    if (lane == 0) red[wid] = m;
    __syncthreads();
    m = red[0];
    #pragma unroll
    for (int w = 1; w < 8; w++) m = fmaxf(m, red[w]);

    float s = 0.f;
    #pragma unroll
    for (int j = 0; j < 8; j++) { e[j] = __expf(e[j] - m); s += e[j]; }
    #pragma unroll
    for (int o = 16; o; o >>= 1) s += __shfl_xor_sync(~0u, s, o);
    __syncthreads();
    if (lane == 0) red[wid] = s;
    __syncthreads();
    s = 0.f;
    #pragma unroll
    for (int w = 0; w < 8; w++) s += red[w];
    const float inv = 1.f / s;

    if (live) {
        uint4 o;
        o.x = pack2(e[0] * inv, e[1] * inv);
        o.y = pack2(e[2] * inv, e[3] * inv);
        o.z = pack2(e[4] * inv, e[5] * inv);
        o.w = pack2(e[6] * inv, e[7] * inv);
        *(uint4*)(prow + i0) = o;
    }
}

// fused fp32 -> fp16 bulk convert for x, w_qkv, w_proj in one launch.
// blocks [0,4096): x, [4096,5632): w_qkv, [5632,6144): w_proj
__global__ __launch_bounds__(256) void cvt_all_k(
    const float* __restrict__ x, __half* __restrict__ xh,
    const float* __restrict__ wq, __half* __restrict__ wqh,
    const float* __restrict__ wp, __half* __restrict__ wph)
{
    const float* in;
    __half* out;
    size_t base;
    const int bx = blockIdx.x;
    if (bx < 4096)      { in = x;  out = xh;  base = (size_t)bx * 2048; }
    else if (bx < 5632) { in = wq; out = wqh; base = (size_t)(bx - 4096) * 2048; }
    else                { in = wp; out = wph; base = (size_t)(bx - 5632) * 2048; }
    const size_t i = base + (size_t)threadIdx.x * 8;
    float4 v0 = *(const float4*)(in + i);
    float4 v1 = *(const float4*)(in + i + 4);
    uint4 o;
    o.x = pack2(v0.x, v0.y); o.y = pack2(v0.z, v0.w);
    o.z = pack2(v1.x, v1.y); o.w = pack2(v1.z, v1.w);
    *(uint4*)(out + i) = o;
}

extern "C" void kernel_launch(void* const* d_in, const int* in_sizes, int n_in,
                              void* d_out, int out_size)
{
    (void)in_sizes; (void)n_in; (void)out_size;
    const float* x      = (const float*)d_in[0];  // [4,2048,1024]
    const float* w_qkv  = (const float*)d_in[1];  // [1024,3072]
    const float* w_proj = (const float*)d_in[2];  // [1024,1024]
    const float* b_proj = (const float*)d_in[3];  // [1024]
    float* out          = (float*)d_out;          // [4,2048,1024]

    __half *xh, *wqkvh, *wprojh, *qkv, *p, *att;
    float *scores;
    cudaGetSymbolAddress((void**)&xh,     g_xh);
    cudaGetSymbolAddress((void**)&wqkvh,  g_wqkvh);
    cudaGetSymbolAddress((void**)&wprojh, g_wprojh);
    cudaGetSymbolAddress((void**)&qkv,    g_qkv);
    cudaGetSymbolAddress((void**)&scores, g_scores);
    cudaGetSymbolAddress((void**)&p,      g_p);
    cudaGetSymbolAddress((void**)&att,    g_att);

    const int D = D_MODEL, T = T_SEQ;
    const dim3 blk(512);

    cudaFuncSetAttribute((const void*)mm_h<__half, 1, false, false, false, false>,
                         cudaFuncAttributeMaxDynamicSharedMemorySize, SMEM_BT);
    cudaFuncSetAttribute((const void*)mm_h<float, 0, true, false, false, true>,
                         cudaFuncAttributeMaxDynamicSharedMemorySize, SMEM_BN);
    cudaFuncSetAttribute((const void*)mm_h<__half, 1, false, true, false, true>,
                         cudaFuncAttributeMaxDynamicSharedMemorySize, SMEM_BT);
    cudaFuncSetAttribute((const void*)mm_h<float, 1, false, false, true, false>,
                         cudaFuncAttributeMaxDynamicSharedMemorySize, SMEM_BT);

    // 0) fused fp32 -> fp16 conversions (one launch)
    cvt_all_k<<<6144, 256>>>(x, xh, w_qkv, wqkvh, w_proj, wprojh);

    // 1) QKV = Xh @ Wqkv -> fp16 : [8192,3072], K=1024, B [K,N]
    mm_h<__half, 1, false, false, false, false>
        <<<dim3(3 * D / 256, B_BATCH * T / 128, 1), blk, SMEM_BT>>>(
        xh, wqkvh, qkv, nullptr, D, D, 3 * D, 3 * D, 0, 0, 0, 1.f);

    // 2) scores = Q @ K^T / 32 (fp32), causal cull, heavy-first; K-matrix [N,K]
    mm_h<float, 0, true, false, false, true>
        <<<dim3(T / 256, T / 128, B_BATCH), blk, SMEM_BN>>>(
        qkv, qkv + D, scores, nullptr, D, 3 * D, 3 * D, T,
        (long)T * 3 * D, (long)T * 3 * D, (long)T * T, 1.f / 32.f);

    // 3) causal softmax -> fp16 P (bounded loads, tail zero to 128-block end)
    softmax_causal_k<<<dim3(T, B_BATCH), 256>>>(scores, p);

    // 4) att = P @ V -> fp16 : causal K-end, heavy-first; V [K,N]
    mm_h<__half, 1, false, true, false, true>
        <<<dim3(D / 256, T / 128, B_BATCH), blk, SMEM_BT>>>(
        p, qkv + 2 * D, att, nullptr, T, T, 3 * D, D,
        (long)T * T, (long)T * 3 * D, (long)T * D, 1.f);

    // 5) out = att @ Wproj + b : [8192,1024], K=1024, B [K,N]
    mm_h<float, 1, false, false, true, false>
        <<<dim3(D / 256, B_BATCH * T / 128, 1), blk, SMEM_BT>>>(
        att, wprojh, out, b_proj, D, D, D, D, 0, 0, 0, 1.f);
}